// round 3
// baseline (speedup 1.0000x reference)
#include <cuda_runtime.h>
#include <math.h>

#define Bn 64
#define Nn 1024
#define Wn 64
#define Rn 4

// ---------------- device scratch (no allocations allowed) ----------------
__device__ float g_ww [Bn*Nn];       // new write weights (B,N)
__device__ float g_fwd[Bn*Rn*Nn];    // fwd_w (B,R,N)
__device__ float g_bwd[Bn*Rn*Nn];    // bwd_w (B,R,N)

__device__ __forceinline__ float softplusf(float x){
    return fmaxf(x, 0.f) + log1pf(expf(-fabsf(x)));
}

// block reduce helpers: require exactly 1024 threads (32 warps)
__device__ __forceinline__ float block_reduce_max(float v, float* s_red, float* s_out,
                                                  int lane, int wid){
#pragma unroll
    for (int o = 16; o; o >>= 1) v = fmaxf(v, __shfl_xor_sync(0xffffffffu, v, o));
    if (lane == 0) s_red[wid] = v;
    __syncthreads();
    if (wid == 0){
        float t = s_red[lane];
#pragma unroll
        for (int o = 16; o; o >>= 1) t = fmaxf(t, __shfl_xor_sync(0xffffffffu, t, o));
        if (lane == 0) *s_out = t;
    }
    __syncthreads();
    return *s_out;
}

__device__ __forceinline__ float block_reduce_sum(float v, float* s_red, float* s_out,
                                                  int lane, int wid){
#pragma unroll
    for (int o = 16; o; o >>= 1) v += __shfl_xor_sync(0xffffffffu, v, o);
    if (lane == 0) s_red[wid] = v;
    __syncthreads();
    if (wid == 0){
        float t = s_red[lane];
#pragma unroll
        for (int o = 16; o; o >>= 1) t += __shfl_xor_sync(0xffffffffu, t, o);
        if (lane == 0) *s_out = t;
    }
    __syncthreads();
    return *s_out;
}

// ============================================================================
// K1: usage, write content (cosine softmax), allocation (sort+scan),
//     write_weights -> g_ww; zero g_fwd/g_bwd.
// One block per batch, 1024 threads.
// ============================================================================
__global__ void __launch_bounds__(1024) k1_kernel(
    const float* __restrict__ memory,      // (B,N,W)
    const float* __restrict__ prw,         // (B,R,N)
    const float* __restrict__ pww,         // (B,1,N)
    const float* __restrict__ pusage,      // (B,N)
    const float* __restrict__ wkeys,       // (B,1,W)
    const float* __restrict__ wstr,        // (B,1)
    const float* __restrict__ fgate,       // (B,R)
    const float* __restrict__ agate,       // (B,1)
    const float* __restrict__ wgate)       // (B,1)
{
    int b   = blockIdx.x;
    int tid = threadIdx.x;
    int lane = tid & 31, wid = tid >> 5;

    __shared__ float s_usage[Nn];
    __shared__ float s_sharp[Nn];   // sharp similarities, later reused as alloc
    __shared__ float s_val[Nn];
    __shared__ int   s_idx[Nn];
    __shared__ float s_scan[Nn];
    __shared__ float s_red[32];
    __shared__ float s_b0, s_b1;

    // ---- usage ----
    {
        float pu = pusage[b*Nn + tid];
        float w0 = pww[b*Nn + tid];
        float u  = pu + (1.f - pu) * w0;        // NW=1: agg_write == pww
        float phi = 1.f;
#pragma unroll
        for (int r = 0; r < Rn; r++){
            float fg = fgate[b*Rn + r];
            phi *= 1.f - fg * prw[(b*Rn + r)*Nn + tid];
        }
        s_usage[tid] = u * phi;
    }

    // ---- write content: cosine similarity, warp per row ----
    float2 key = *(const float2*)(wkeys + b*Wn + lane*2);
    float kn = key.x*key.x + key.y*key.y;
#pragma unroll
    for (int o = 16; o; o >>= 1) kn += __shfl_xor_sync(0xffffffffu, kn, o);
    kn = sqrtf(kn + 1e-6f);
    float sp = softplusf(wstr[b]);

    for (int n = wid; n < Nn; n += 32){
        float2 m = ((const float2*)(memory + ((size_t)(b*Nn + n))*Wn))[lane];
        float d = key.x*m.x + key.y*m.y;
        float q = m.x*m.x + m.y*m.y;
#pragma unroll
        for (int o = 16; o; o >>= 1){
            d += __shfl_xor_sync(0xffffffffu, d, o);
            q += __shfl_xor_sync(0xffffffffu, q, o);
        }
        if (lane == 0){
            float mnorm = sqrtf(q + 1e-6f);
            s_sharp[n] = d / (kn * mnorm + 1e-6f) * sp;
        }
    }
    __syncthreads();

    // ---- softmax over N ----
    float v  = s_sharp[tid];
    float mx = block_reduce_max(v, s_red, &s_b0, lane, wid);
    float e  = expf(v - mx);
    float sm = block_reduce_sum(e, s_red, &s_b1, lane, wid);
    float content = e / sm;

    // ---- allocation: bitonic sort of nonusage (desc, tie-break asc index) ----
    float usage = s_usage[tid];
    float up   = 1e-6f + (1.f - 1e-6f) * usage;
    float nonu = 1.f - up;
    s_val[tid] = nonu;
    s_idx[tid] = tid;
    __syncthreads();
    for (int k = 2; k <= Nn; k <<= 1){
        for (int j = k >> 1; j > 0; j >>= 1){
            int ixj = tid ^ j;
            if (ixj > tid){
                float a = s_val[tid], c = s_val[ixj];
                int   ia = s_idx[tid], ic = s_idx[ixj];
                bool less = (a < c) || (a == c && ia > ic);
                bool doswap = ((tid & k) == 0) ? less : !less;
                if (doswap){
                    s_val[tid] = c; s_val[ixj] = a;
                    s_idx[tid] = ic; s_idx[ixj] = ia;
                }
            }
            __syncthreads();
        }
    }
    // inclusive product scan of sorted_usage (Hillis-Steele)
    float snon = s_val[tid];
    s_scan[tid] = 1.f - snon;
    __syncthreads();
    for (int off = 1; off < Nn; off <<= 1){
        float t = (tid >= off) ? s_scan[tid - off] : 1.f;
        __syncthreads();
        if (tid >= off) s_scan[tid] *= t;
        __syncthreads();
    }
    float pexcl = (tid == 0) ? 1.f : s_scan[tid - 1];
    float salloc = snon * pexcl;
    int dest = s_idx[tid];
    __syncthreads();           // everyone done reading s_sharp (content in regs)
    s_sharp[dest] = salloc;    // scatter alloc back
    __syncthreads();
    float alloc = s_sharp[tid];

    // ---- write weights ----
    float ag = agate[b], wg = wgate[b];
    float wwn = wg * (ag * alloc + (1.f - ag) * content);
    g_ww[b*Nn + tid] = wwn;

    // zero fwd/bwd scratch for this batch
    for (int i = tid; i < Rn*Nn; i += 1024){
        g_fwd[b*Rn*Nn + i] = 0.f;
        g_bwd[b*Rn*Nn + i] = 0.f;
    }
}

// ============================================================================
// K2: fused link update + fwd/bwd contractions.
//   L[n][m] = (n!=m) * ((1-ww[n]-ww[m])*prev_link[n][m] + ww[n]*prec[m])
//   fwd[r][n] = sum_m prw[r][m]*L[n][m]   (row reduce, shuffle+smem, no atomics)
//   bwd[r][m] = sum_n prw[r][n]*L[n][m]   (thread-local regs, atomicAdd at end)
// grid (16 row-tiles, 64 batches) x 256 threads; thread owns 4 columns.
// ============================================================================
__global__ void __launch_bounds__(256) k2_kernel(
    const float* __restrict__ link,    // (B,1,N,N)
    const float* __restrict__ prw,     // (B,R,N)
    const float* __restrict__ prec)    // (B,1,N)
{
    int b  = blockIdx.y;
    int n0 = blockIdx.x * 64;
    int t  = threadIdx.x;
    int lane = t & 31, wid = t >> 5;

    __shared__ float4 s_prw[Nn];     // [n] -> prw[0..3][n]
    __shared__ float  s_ww [Nn];
    __shared__ float  s_fwd[64][32]; // [row_local][r*8 + warp]

    for (int i = t; i < Nn; i += 256){
        float4 p;
        p.x = prw[(b*Rn + 0)*Nn + i];
        p.y = prw[(b*Rn + 1)*Nn + i];
        p.z = prw[(b*Rn + 2)*Nn + i];
        p.w = prw[(b*Rn + 3)*Nn + i];
        s_prw[i] = p;
        s_ww[i]  = g_ww[b*Nn + i];
    }
    __syncthreads();

    int m0 = t * 4;
    // hoisted per-column constants
    float wwm[4], pcmv[4], pjm[4][4];   // pjm[j][r] = prw[r][m0+j]
#pragma unroll
    for (int j = 0; j < 4; j++){
        wwm[j] = s_ww[m0 + j];
        float4 pj = s_prw[m0 + j];
        pjm[j][0] = pj.x; pjm[j][1] = pj.y; pjm[j][2] = pj.z; pjm[j][3] = pj.w;
    }
    {
        float4 pc = *(const float4*)(prec + b*Nn + m0);
        pcmv[0] = pc.x; pcmv[1] = pc.y; pcmv[2] = pc.z; pcmv[3] = pc.w;
    }

    float bacc[4][4];
#pragma unroll
    for (int r = 0; r < 4; r++)
#pragma unroll
        for (int j = 0; j < 4; j++) bacc[r][j] = 0.f;

    const float* Lb = link + (size_t)b * Nn * Nn;

#pragma unroll 2
    for (int n = n0; n < n0 + 64; n++){
        float wn = s_ww[n];
        float cn = 1.f - wn;
        float4 pn = s_prw[n];
        float pnr[4] = {pn.x, pn.y, pn.z, pn.w};

        float4 P = *(const float4*)(Lb + (size_t)n * Nn + m0);
        float Pv[4] = {P.x, P.y, P.z, P.w};

        float lk[4];
#pragma unroll
        for (int j = 0; j < 4; j++)
            lk[j] = fmaf(cn - wwm[j], Pv[j], wn * pcmv[j]);
#pragma unroll
        for (int j = 0; j < 4; j++)
            if (n == m0 + j) lk[j] = 0.f;   // zero diagonal

        // fwd partials for this row
        float fr[4];
#pragma unroll
        for (int r = 0; r < 4; r++){
            float f = 0.f;
#pragma unroll
            for (int j = 0; j < 4; j++) f = fmaf(pjm[j][r], lk[j], f);
            fr[r] = f;
        }
#pragma unroll
        for (int o = 16; o; o >>= 1){
            fr[0] += __shfl_xor_sync(0xffffffffu, fr[0], o);
            fr[1] += __shfl_xor_sync(0xffffffffu, fr[1], o);
            fr[2] += __shfl_xor_sync(0xffffffffu, fr[2], o);
            fr[3] += __shfl_xor_sync(0xffffffffu, fr[3], o);
        }
        if (lane == 0){
            int nl = n - n0;
            s_fwd[nl][0*8 + wid] = fr[0];
            s_fwd[nl][1*8 + wid] = fr[1];
            s_fwd[nl][2*8 + wid] = fr[2];
            s_fwd[nl][3*8 + wid] = fr[3];
        }

        // bwd accumulation (thread-local over rows)
#pragma unroll
        for (int r = 0; r < 4; r++)
#pragma unroll
            for (int j = 0; j < 4; j++)
                bacc[r][j] = fmaf(pnr[r], lk[j], bacc[r][j]);
    }
    __syncthreads();

    // fwd final: one thread per (row_local, r)
    {
        int nl = t >> 2, r = t & 3;
        float s = 0.f;
#pragma unroll
        for (int w = 0; w < 8; w++) s += s_fwd[nl][r*8 + w];
        g_fwd[(b*Rn + r)*Nn + n0 + nl] = s;
    }

    // bwd: atomic add (16 tiles contend per address)
    float* bw = g_bwd + (size_t)b * Rn * Nn;
#pragma unroll
    for (int r = 0; r < 4; r++)
#pragma unroll
        for (int j = 0; j < 4; j++)
            atomicAdd(&bw[r*Nn + m0 + j], bacc[r][j]);
}

// ============================================================================
// K3: memory_new (on the fly), read content cosine softmax, read mode softmax,
//     read weights, read words. One block per batch, 1024 threads.
//     read_words = G - e*H + wv*S with
//       G[r][k] = sum_n rw[r][n]*mem[n][k]
//       H[r][k] = sum_n (rw[r][n]*ww[n])*mem[n][k]
//       S[r]    = sum_n rw[r][n]*ww[n]
// ============================================================================
__global__ void __launch_bounds__(1024) k3_kernel(
    const float* __restrict__ memory,   // (B,N,W)
    const float* __restrict__ rkeys,    // (B,R,W)
    const float* __restrict__ rstr,     // (B,R)
    const float* __restrict__ wvec,     // (B,1,W)
    const float* __restrict__ evec,     // (B,1,W)
    const float* __restrict__ rmode,    // (B,R,3)
    float* __restrict__ out)            // (B,R,W)
{
    int b   = blockIdx.x;
    int tid = threadIdx.x;
    int lane = tid & 31, wid = tid >> 5;

    __shared__ float  s_rw[Rn][Nn];   // sharp -> read_weights (16KB)
    __shared__ float  s_ww[Nn];
    __shared__ float  s_red[32];
    __shared__ float  s_b0, s_b1;
    __shared__ float2 s_G[8][Rn][32];
    __shared__ float2 s_H[8][Rn][32];
    __shared__ float  s_S[8][Rn];

    s_ww[tid] = g_ww[b*Nn + tid];
    __syncthreads();

    // per-lane key / vector registers
    float2 k0 = *(const float2*)(rkeys + (b*Rn + 0)*Wn + lane*2);
    float2 k1 = *(const float2*)(rkeys + (b*Rn + 1)*Wn + lane*2);
    float2 k2 = *(const float2*)(rkeys + (b*Rn + 2)*Wn + lane*2);
    float2 k3 = *(const float2*)(rkeys + (b*Rn + 3)*Wn + lane*2);
    float2 ev = *(const float2*)(evec + b*Wn + lane*2);
    float2 wv = *(const float2*)(wvec + b*Wn + lane*2);

    float q0 = k0.x*k0.x + k0.y*k0.y;
    float q1 = k1.x*k1.x + k1.y*k1.y;
    float q2 = k2.x*k2.x + k2.y*k2.y;
    float q3 = k3.x*k3.x + k3.y*k3.y;
#pragma unroll
    for (int o = 16; o; o >>= 1){
        q0 += __shfl_xor_sync(0xffffffffu, q0, o);
        q1 += __shfl_xor_sync(0xffffffffu, q1, o);
        q2 += __shfl_xor_sync(0xffffffffu, q2, o);
        q3 += __shfl_xor_sync(0xffffffffu, q3, o);
    }
    float kn0 = sqrtf(q0 + 1e-6f), kn1 = sqrtf(q1 + 1e-6f);
    float kn2 = sqrtf(q2 + 1e-6f), kn3 = sqrtf(q3 + 1e-6f);
    float sp0 = softplusf(rstr[b*Rn + 0]);
    float sp1 = softplusf(rstr[b*Rn + 1]);
    float sp2 = softplusf(rstr[b*Rn + 2]);
    float sp3 = softplusf(rstr[b*Rn + 3]);

    // phase A: sharp[r][n] from memory_new rows (warp per row)
    for (int n = wid; n < Nn; n += 32){
        float2 m = ((const float2*)(memory + ((size_t)(b*Nn + n))*Wn))[lane];
        float w = s_ww[n];
        float2 mn;
        mn.x = fmaf(m.x, 1.f - w*ev.x, w*wv.x);
        mn.y = fmaf(m.y, 1.f - w*ev.y, w*wv.y);
        float d0 = mn.x*k0.x + mn.y*k0.y;
        float d1 = mn.x*k1.x + mn.y*k1.y;
        float d2 = mn.x*k2.x + mn.y*k2.y;
        float d3 = mn.x*k3.x + mn.y*k3.y;
        float qq = mn.x*mn.x + mn.y*mn.y;
#pragma unroll
        for (int o = 16; o; o >>= 1){
            d0 += __shfl_xor_sync(0xffffffffu, d0, o);
            d1 += __shfl_xor_sync(0xffffffffu, d1, o);
            d2 += __shfl_xor_sync(0xffffffffu, d2, o);
            d3 += __shfl_xor_sync(0xffffffffu, d3, o);
            qq += __shfl_xor_sync(0xffffffffu, qq, o);
        }
        if (lane == 0){
            float mnorm = sqrtf(qq + 1e-6f);
            s_rw[0][n] = d0 / (kn0 * mnorm + 1e-6f) * sp0;
            s_rw[1][n] = d1 / (kn1 * mnorm + 1e-6f) * sp1;
            s_rw[2][n] = d2 / (kn2 * mnorm + 1e-6f) * sp2;
            s_rw[3][n] = d3 / (kn3 * mnorm + 1e-6f) * sp3;
        }
    }
    __syncthreads();

    // phase B: softmax per r + combine with fwd/bwd via read-mode softmax
    for (int r = 0; r < Rn; r++){
        float v  = s_rw[r][tid];
        float mx = block_reduce_max(v, s_red, &s_b0, lane, wid);
        float e  = expf(v - mx);
        float sm = block_reduce_sum(e, s_red, &s_b1, lane, wid);
        float rc = e / sm;

        float m0v = rmode[(b*Rn + r)*3 + 0];
        float m1v = rmode[(b*Rn + r)*3 + 1];
        float m2v = rmode[(b*Rn + r)*3 + 2];
        float mm = fmaxf(m0v, fmaxf(m1v, m2v));
        float e0 = expf(m0v - mm), e1 = expf(m1v - mm), e2 = expf(m2v - mm);
        float inv = 1.f / (e0 + e1 + e2);
        float bm = e0 * inv, fm = e1 * inv, cm = e2 * inv;

        float rw = cm * rc
                 + fm * g_fwd[(b*Rn + r)*Nn + tid]
                 + bm * g_bwd[(b*Rn + r)*Nn + tid];
        s_rw[r][tid] = rw;
    }
    __syncthreads();

    // phase C: read words
    {
        int z  = tid >> 7;          // 0..7 (splits N)
        int r  = (tid >> 5) & 3;    // 0..3
        int kh = tid & 31;          // 0..31 -> k = 2*kh
        const float* mp = memory + (size_t)(b*Nn)*Wn + kh*2;
        float2 G = make_float2(0.f, 0.f);
        float2 H = make_float2(0.f, 0.f);
        float  S = 0.f;
        int nbase = z * 128;
#pragma unroll 4
        for (int i = 0; i < 128; i++){
            int n = nbase + i;
            float2 m = *(const float2*)(mp + (size_t)n * Wn);
            float rwv = s_rw[r][n];
            float w   = s_ww[n];
            float t2  = rwv * w;
            G.x = fmaf(rwv, m.x, G.x); G.y = fmaf(rwv, m.y, G.y);
            H.x = fmaf(t2,  m.x, H.x); H.y = fmaf(t2,  m.y, H.y);
            S += t2;
        }
        s_G[z][r][kh] = G;
        s_H[z][r][kh] = H;
        if (kh == 0) s_S[z][r] = S;
    }
    __syncthreads();
    if (tid < 128){
        int r2 = tid >> 5, kh2 = tid & 31;
        float gx = 0.f, gy = 0.f, hx = 0.f, hy = 0.f, s = 0.f;
#pragma unroll
        for (int zz = 0; zz < 8; zz++){
            float2 g = s_G[zz][r2][kh2]; gx += g.x; gy += g.y;
            float2 h = s_H[zz][r2][kh2]; hx += h.x; hy += h.y;
            s += s_S[zz][r2];
        }
        float2 e = *(const float2*)(evec + b*Wn + kh2*2);
        float2 w = *(const float2*)(wvec + b*Wn + kh2*2);
        out[(b*Rn + r2)*Wn + kh2*2    ] = gx - e.x*hx + w.x*s;
        out[(b*Rn + r2)*Wn + kh2*2 + 1] = gy - e.y*hy + w.y*s;
    }
}

// ============================================================================
extern "C" void kernel_launch(void* const* d_in, const int* in_sizes, int n_in,
                              void* d_out, int out_size)
{
    const float* memory  = (const float*)d_in[0];
    const float* prw     = (const float*)d_in[1];
    const float* pww     = (const float*)d_in[2];
    const float* pusage  = (const float*)d_in[3];
    const float* plink   = (const float*)d_in[4];
    const float* pprec   = (const float*)d_in[5];
    const float* rkeys   = (const float*)d_in[6];
    const float* rstr    = (const float*)d_in[7];
    const float* wkeys   = (const float*)d_in[8];
    const float* wstr    = (const float*)d_in[9];
    const float* wvec    = (const float*)d_in[10];
    const float* evec    = (const float*)d_in[11];
    const float* fgate   = (const float*)d_in[12];
    const float* agate   = (const float*)d_in[13];
    const float* wgate   = (const float*)d_in[14];
    const float* rmode   = (const float*)d_in[15];
    float* out = (float*)d_out;

    k1_kernel<<<Bn, 1024>>>(memory, prw, pww, pusage, wkeys, wstr,
                            fgate, agate, wgate);
    k2_kernel<<<dim3(16, Bn), 256>>>(plink, prw, pprec);
    k3_kernel<<<Bn, 1024>>>(memory, rkeys, rstr, wvec, evec, rmode, out);
}